// round 3
// baseline (speedup 1.0000x reference)
#include <cuda_runtime.h>
#include <cstdint>
#include <cstddef>

// ---------------------------------------------------------------------------
// Persistent-register 2-layer GRU. 16 clusters x 8 CTAs x 256 threads.
// Each lane owns ONE 200-float weight row in REGISTERS for the whole kernel:
//   tid   0- 74 : layer0 W_hh0 rows (3 gates x 25 j)      -> active phase A
//   tid  75-149 : layer1 W_hh1 rows (h-part)              -> active phase A
//   tid 150-224 : layer1 W_ih1 rows (x-part)              -> active phase B
//   tid 225-228 : W_fc rows (FC output, pipelined 1 step behind)
// h vectors live in smem [parity][b][200]; matvec reads are warp-broadcast
// LDS.128. Dot products are stored to LOCAL smem (row j owned by CTA j/25),
// so only h-state broadcast crosses the cluster (2 cluster syncs/step).
// ---------------------------------------------------------------------------

#define HDIM   200
#define TSTEPS 1024
#define NB     8
#define NTHR   256
#define CLSZ   8

typedef unsigned long long u64;

// ---- shared memory layout (float offsets) ----
enum {
  O_DA   = 0,                 // layer0 dots [3][25][8]
  O_DBH  = 600,               // layer1 h-part dots [3][25][8]
  O_DBX  = 1200,              // layer1 x-part dots [3][25][8]
  O_H0   = 1824,              // h0 [2][8][200]
  O_H1   = O_H0 + 2*NB*HDIM,  // h1 [2][8][200]
  O_INB  = O_H1 + 2*NB*HDIM,  // inputs [8][8]
  O_WI0  = O_INB + 64,        // W_ih0 slice [3][25][8]
  O_BR0  = O_WI0 + 600,
  O_BZ0  = O_BR0 + 25,
  O_BN0X = O_BZ0 + 25,
  O_BN0H = O_BN0X + 25,
  O_BR1  = O_BN0H + 25,
  O_BZ1  = O_BR1 + 25,
  O_BN1X = O_BZ1 + 25,
  O_BN1H = O_BN1X + 25,
  O_BFC  = O_BN1H + 25,
  SMEM_F = O_BFC + 4
};

__shared__ float smem[SMEM_F];

#define FMA2(acc_, a_, b_) \
  asm("fma.rn.f32x2 %0, %1, %2, %0;" : "+l"(acc_) : "l"(a_), "l"(b_))
#define ADD2(d_, a_, b_) \
  asm("add.rn.f32x2 %0, %1, %2;" : "=l"(d_) : "l"(a_), "l"(b_))
#define PACK2(d_, x_, y_) \
  asm("mov.b64 %0, {%1, %2};" : "=l"(d_) : "f"(x_), "f"(y_))

__device__ __forceinline__ float red2(u64 v) {
  float lo, hi;
  asm("mov.b64 {%0,%1}, %2;" : "=f"(lo), "=f"(hi) : "l"(v));
  return lo + hi;
}
__device__ __forceinline__ void cluster_sync() {
  asm volatile("barrier.cluster.arrive.aligned;" ::: "memory");
  asm volatile("barrier.cluster.wait.aligned;" ::: "memory");
}
__device__ __forceinline__ float sigmoid_f(float x) {
  return __fdividef(1.0f, 1.0f + __expf(-x));
}
__device__ __forceinline__ float tanh_f(float x) {
  float e = __expf(-2.0f * x);
  return __fdividef(2.0f, 1.0f + e) - 1.0f;
}

// dot(w[200 regs], h[b][0:200]) for 8 batches; dots -> smem[dotoff + b]
__device__ __forceinline__ void matvec8(const u64* w, int voff, int dotoff) {
  #pragma unroll 1
  for (int b = 0; b < NB; b++) {
    const ulonglong2* hv = (const ulonglong2*)(smem + voff + b*HDIM);
    u64 a0 = 0, a1 = 0, a2 = 0, a3 = 0;
    #pragma unroll
    for (int i = 0; i < 25; i++) {
      ulonglong2 A = hv[2*i], Bv = hv[2*i+1];
      FMA2(a0, w[4*i],   A.x);
      FMA2(a1, w[4*i+1], A.y);
      FMA2(a2, w[4*i+2], Bv.x);
      FMA2(a3, w[4*i+3], Bv.y);
    }
    ADD2(a0, a0, a1); ADD2(a2, a2, a3); ADD2(a0, a0, a2);
    smem[dotoff + b] = red2(a0);
  }
}

__global__ void __launch_bounds__(NTHR, 1) __cluster_dims__(CLSZ, 1, 1)
gru2_kernel(const float* __restrict__ x,
            const float* __restrict__ W_ih0, const float* __restrict__ W_hh0,
            const float* __restrict__ b_ih0, const float* __restrict__ b_hh0,
            const float* __restrict__ W_ih1, const float* __restrict__ W_hh1,
            const float* __restrict__ b_ih1, const float* __restrict__ b_hh1,
            const float* __restrict__ W_fc,  const float* __restrict__ b_fc,
            float* __restrict__ out)
{
  const int tid = threadIdx.x;
  uint32_t rank;
  asm("mov.u32 %0, %%cluster_ctarank;" : "=r"(rank));
  const int g = blockIdx.x >> 3;   // batch group (cluster id)
  uint32_t sb = (uint32_t)__cvta_generic_to_shared(smem);

  // ---- per-lane role & weight-row source ----
  const float* wsrc = nullptr;
  int dotoff = 0, voffA_base = 0;  // voffA_base: which h buffer in phase A
  if (tid < 75) {
    int gt = tid / 25, jl = tid % 25;
    wsrc = W_hh0 + (size_t)(gt*HDIM + (int)rank*25 + jl) * HDIM;
    dotoff = O_DA + gt*200 + jl*8;
    voffA_base = O_H0;
  } else if (tid < 150) {
    int u = tid - 75, gt = u / 25, jl = u % 25;
    wsrc = W_hh1 + (size_t)(gt*HDIM + (int)rank*25 + jl) * HDIM;
    dotoff = O_DBH + gt*200 + jl*8;
    voffA_base = O_H1;
  } else if (tid < 225) {
    int u = tid - 150, gt = u / 25, jl = u % 25;
    wsrc = W_ih1 + (size_t)(gt*HDIM + (int)rank*25 + jl) * HDIM;
    dotoff = O_DBX + gt*200 + jl*8;
  } else if (tid < 229) {
    wsrc = W_fc + (size_t)(tid - 225) * HDIM;
  }

  // ---- load this lane's weight row into registers ----
  u64 w[100];
  if (wsrc) {
    #pragma unroll
    for (int i = 0; i < 50; i++) {
      float4 f = ((const float4*)wsrc)[i];
      PACK2(w[2*i],   f.x, f.y);
      PACK2(w[2*i+1], f.z, f.w);
    }
  }

  // ---- init smem: zero h, small weights, biases, step-0 inputs ----
  for (int i = tid; i < 2*NB*HDIM; i += NTHR) {
    smem[O_H0 + i] = 0.f; smem[O_H1 + i] = 0.f;
  }
  for (int i = tid; i < 600; i += NTHR)
    smem[O_WI0 + i] = W_ih0[(size_t)((i/200)*HDIM + (int)rank*25) * 8 + (i % 200)];
  if (tid < 25) {
    int J = (int)rank*25 + tid;
    smem[O_BR0  + tid] = b_ih0[J]        + b_hh0[J];
    smem[O_BZ0  + tid] = b_ih0[HDIM+J]   + b_hh0[HDIM+J];
    smem[O_BN0X + tid] = b_ih0[2*HDIM+J];
    smem[O_BN0H + tid] = b_hh0[2*HDIM+J];
    smem[O_BR1  + tid] = b_ih1[J]        + b_hh1[J];
    smem[O_BZ1  + tid] = b_ih1[HDIM+J]   + b_hh1[HDIM+J];
    smem[O_BN1X + tid] = b_ih1[2*HDIM+J];
    smem[O_BN1H + tid] = b_hh1[2*HDIM+J];
  }
  if (tid < 4) smem[O_BFC + tid] = b_fc[tid];
  if (tid < NB) {
    const float* xr = x + (size_t)(g*NB + tid) * TSTEPS * 8;
    float* ib = smem + O_INB + tid*8;
    ib[0] = 1.f; ib[1] = 1.f; ib[2] = 1.f; ib[3] = 1.f;
    ib[4] = xr[4]; ib[5] = xr[5]; ib[6] = xr[6]; ib[7] = xr[7];
  }
  cluster_sync();

  for (int t = 0; t < TSTEPS; t++) {
    const int p = t & 1, q = p ^ 1;

    // ===== W1: A + B-h matvecs (read h0[p], h1[p]); FC for t-1; x prefetch
    float4 xnext = make_float4(0.f, 0.f, 0.f, 0.f);
    if (tid < NB)
      xnext = *(const float4*)(x + ((size_t)(g*NB + tid) * TSTEPS + t) * 8);

    if (tid < 150) {
      matvec8(w, voffA_base + p*(NB*HDIM), dotoff);
    } else if (tid >= 225 && tid < 229 && t > 0) {
      // FC on h1[p] (state after step t-1) for output t-1
      const ulonglong2* hv =
          (const ulonglong2*)(smem + O_H1 + p*(NB*HDIM) + (int)rank*HDIM);
      u64 a0 = 0, a1 = 0, a2 = 0, a3 = 0;
      #pragma unroll
      for (int i = 0; i < 25; i++) {
        ulonglong2 A = hv[2*i], Bv = hv[2*i+1];
        FMA2(a0, w[4*i], A.x);   FMA2(a1, w[4*i+1], A.y);
        FMA2(a2, w[4*i+2], Bv.x); FMA2(a3, w[4*i+3], Bv.y);
      }
      ADD2(a0, a0, a1); ADD2(a2, a2, a3); ADD2(a0, a0, a2);
      int o = tid - 225;
      float v = tanh_f(red2(a0) + smem[O_BFC + o]);
      out[((size_t)(g*NB + (int)rank) * TSTEPS + (t-1)) * 4 + o] = v;
    }
    __syncthreads();

    // ===== W2: cell0 update (local dots), broadcast h0new cluster-wide
    if (tid < 200) {
      int jl = tid >> 3, b = tid & 7;
      int gj = (int)rank*25 + jl;
      float dr = smem[O_DA +       jl*8 + b];
      float dz = smem[O_DA + 200 + jl*8 + b];
      float dn = smem[O_DA + 400 + jl*8 + b];
      float xr = smem[O_BR0 + jl], xz = smem[O_BZ0 + jl], xn = smem[O_BN0X + jl];
      #pragma unroll
      for (int c = 0; c < 8; c++) {
        float ic = smem[O_INB + b*8 + c];
        xr = fmaf(smem[O_WI0 +       jl*8 + c], ic, xr);
        xz = fmaf(smem[O_WI0 + 200 + jl*8 + c], ic, xz);
        xn = fmaf(smem[O_WI0 + 400 + jl*8 + c], ic, xn);
      }
      float r = sigmoid_f(xr + dr);
      float z = sigmoid_f(xz + dz);
      float n = tanh_f(xn + r * (dn + smem[O_BN0H + jl]));
      float h_o = smem[O_H0 + p*(NB*HDIM) + b*HDIM + gj];
      float hn = n + z * (h_o - n);
      uint32_t la = sb + (uint32_t)(O_H0 + q*(NB*HDIM) + b*HDIM + gj) * 4;
      #pragma unroll
      for (int rr = 0; rr < CLSZ; rr++) {
        uint32_t ra;
        asm("mapa.shared::cluster.u32 %0, %1, %2;" : "=r"(ra) : "r"(la), "r"(rr));
        asm volatile("st.shared::cluster.f32 [%0], %1;" :: "r"(ra), "f"(hn) : "memory");
      }
    }
    cluster_sync();   // h0new visible everywhere

    // ===== W3: B-x matvec on h0new; stage next step's inputs
    if (tid >= 150 && tid < 225)
      matvec8(w, O_H0 + q*(NB*HDIM), dotoff);
    if (tid < NB) {
      float* ib = smem + O_INB + tid*8;
      ib[0] = xnext.x; ib[1] = xnext.y; ib[2] = xnext.z; ib[3] = xnext.w;
    }
    __syncthreads();

    // ===== W4: cell1 update, broadcast h1new cluster-wide
    if (tid < 200) {
      int jl = tid >> 3, b = tid & 7;
      int gj = (int)rank*25 + jl;
      float xr = smem[O_DBX +       jl*8 + b];
      float xz = smem[O_DBX + 200 + jl*8 + b];
      float xn = smem[O_DBX + 400 + jl*8 + b];
      float hr = smem[O_DBH +       jl*8 + b];
      float hz = smem[O_DBH + 200 + jl*8 + b];
      float hn_ = smem[O_DBH + 400 + jl*8 + b];
      float r = sigmoid_f(xr + hr + smem[O_BR1 + jl]);
      float z = sigmoid_f(xz + hz + smem[O_BZ1 + jl]);
      float n = tanh_f(xn + smem[O_BN1X + jl] + r * (hn_ + smem[O_BN1H + jl]));
      float h_o = smem[O_H1 + p*(NB*HDIM) + b*HDIM + gj];
      float hn = n + z * (h_o - n);
      uint32_t la = sb + (uint32_t)(O_H1 + q*(NB*HDIM) + b*HDIM + gj) * 4;
      #pragma unroll
      for (int rr = 0; rr < CLSZ; rr++) {
        uint32_t ra;
        asm("mapa.shared::cluster.u32 %0, %1, %2;" : "=r"(ra) : "r"(la), "r"(rr));
        asm volatile("st.shared::cluster.f32 [%0], %1;" :: "r"(ra), "f"(hn) : "memory");
      }
    }
    cluster_sync();   // h1new visible everywhere
  }

  // ---- drain: FC for t = 1023 (final h1 lives in parity 0) ----
  if (tid >= 225 && tid < 229) {
    const ulonglong2* hv = (const ulonglong2*)(smem + O_H1 + (int)rank*HDIM);
    u64 a0 = 0, a1 = 0, a2 = 0, a3 = 0;
    #pragma unroll
    for (int i = 0; i < 25; i++) {
      ulonglong2 A = hv[2*i], Bv = hv[2*i+1];
      FMA2(a0, w[4*i], A.x);   FMA2(a1, w[4*i+1], A.y);
      FMA2(a2, w[4*i+2], Bv.x); FMA2(a3, w[4*i+3], Bv.y);
    }
    ADD2(a0, a0, a1); ADD2(a2, a2, a3); ADD2(a0, a0, a2);
    int o = tid - 225;
    float v = tanh_f(red2(a0) + smem[O_BFC + o]);
    out[((size_t)(g*NB + (int)rank) * TSTEPS + (TSTEPS-1)) * 4 + o] = v;
  }
}

extern "C" void kernel_launch(void* const* d_in, const int* in_sizes, int n_in,
                              void* d_out, int out_size) {
  (void)in_sizes; (void)n_in; (void)out_size;
  const float* x     = (const float*)d_in[0];
  const float* W_ih0 = (const float*)d_in[1];
  const float* W_hh0 = (const float*)d_in[2];
  const float* b_ih0 = (const float*)d_in[3];
  const float* b_hh0 = (const float*)d_in[4];
  const float* W_ih1 = (const float*)d_in[5];
  const float* W_hh1 = (const float*)d_in[6];
  const float* b_ih1 = (const float*)d_in[7];
  const float* b_hh1 = (const float*)d_in[8];
  const float* W_fc  = (const float*)d_in[9];
  const float* b_fc  = (const float*)d_in[10];

  gru2_kernel<<<128, NTHR>>>(x, W_ih0, W_hh0, b_ih0, b_hh0,
                             W_ih1, W_hh1, b_ih1, b_hh1,
                             W_fc, b_fc, (float*)d_out);
}